// round 1
// baseline (speedup 1.0000x reference)
#include <cuda_runtime.h>
#include <cstdint>

#define SEQ   512
#define BATCH 512
#define IDIM  300
#define HDIM  300
#define NP    320          // padded hidden for XP layout
#define JH    152          // per-CTA j-half in scan (2*152 = 304 >= 300)
#define MTOT  (SEQ*BATCH)

#define BM 128
#define BN 160
#define BK 20

#define STHREADS 160
#define HSTRIDE  8
#define HBUF     (304*HSTRIDE)   // one h buffer: [304 j][8 b]
#define WSZ      (IDIM*JH)

// -------- scratch (static device globals; no allocations) --------
__device__ float g_XP[(long long)MTOT * NP];     // ~335 MB
__device__ float g_WihT[IDIM * NP];              // W_ih transposed+padded: [i][j]
__device__ float g_WT[2 * IDIM * JH];            // per-half W_hh transposed: [r][k][jj]
__device__ float g_bias[NP];                     // b_ih + b_hh (padded with 0)

// -------- f32x2 helpers (Blackwell packed fp32, PTX-only) --------
__device__ __forceinline__ unsigned long long pack2(float lo, float hi) {
    unsigned long long r;
    asm("mov.b64 %0, {%1, %2};" : "=l"(r) : "f"(lo), "f"(hi));
    return r;
}
__device__ __forceinline__ unsigned long long bcast2(float v) {
    unsigned long long r;
    asm("mov.b64 %0, {%1, %1};" : "=l"(r) : "f"(v));
    return r;
}
__device__ __forceinline__ void ffma2(unsigned long long& d, unsigned long long a, unsigned long long b) {
    asm("fma.rn.f32x2 %0, %1, %2, %3;" : "=l"(d) : "l"(a), "l"(b), "l"(d));
}
__device__ __forceinline__ void unpack2(unsigned long long v, float& lo, float& hi) {
    asm("mov.b64 {%0, %1}, %2;" : "=f"(lo), "=f"(hi) : "l"(v));
}
__device__ __forceinline__ uint32_t smem_u32(const void* p) {
    uint32_t a;
    asm("{ .reg .u64 t; cvta.to.shared.u64 t, %1; cvt.u32.u64 %0, t; }" : "=r"(a) : "l"(p));
    return a;
}

// -------- prep: transposes / padding / bias fold --------
__global__ void prep_kernel(const float* __restrict__ Wih, const float* __restrict__ Whh,
                            const float* __restrict__ bih, const float* __restrict__ bhh) {
    int i = blockIdx.x * blockDim.x + threadIdx.x;
    if (i < IDIM * NP) {
        int r = i / NP, j = i % NP;
        g_WihT[i] = (j < HDIM) ? Wih[j * IDIM + r] : 0.f;
    }
    if (i < 2 * IDIM * JH) {
        int rr  = i / (IDIM * JH);
        int rem = i % (IDIM * JH);
        int k = rem / JH, jj = rem % JH;
        int j = rr * JH + jj;
        g_WT[i] = (j < HDIM) ? Whh[j * HDIM + k] : 0.f;
    }
    if (i < NP) g_bias[i] = (i < HDIM) ? (bih[i] + bhh[i]) : 0.f;
}

// -------- x_proj GEMM: XP[m][j] = IN[m][:] . W_ih[j][:] + bias[j] --------
__global__ __launch_bounds__(256) void gemm_xproj(const float* __restrict__ IN) {
    __shared__ float As[BM][BK + 1];  // [m][k], padded
    __shared__ float Bs[BK][BN];      // [k][n], n contiguous
    int tid = threadIdx.x;
    int m0 = blockIdx.y * BM;
    int n0 = blockIdx.x * BN;
    int mth = tid >> 4, nth = tid & 15;
    int tm0 = mth * 8, tn0 = nth * 10;

    unsigned long long acc[8][5];
    #pragma unroll
    for (int i = 0; i < 8; i++)
        #pragma unroll
        for (int u = 0; u < 5; u++) acc[i][u] = 0ull;

    float bias[10];
    #pragma unroll
    for (int u = 0; u < 10; u++) bias[u] = g_bias[n0 + tn0 + u];

    for (int kk = 0; kk < IDIM; kk += BK) {
        #pragma unroll
        for (int l = 0; l < (BM * BK) / 256; l++) {
            int idx = tid + l * 256;
            int k = idx % BK, m = idx / BK;
            As[m][k] = IN[(long long)(m0 + m) * IDIM + kk + k];
        }
        for (int idx = tid * 4; idx < BK * BN; idx += 256 * 4) {
            int k = idx / BN, n = idx % BN;
            *(float4*)&Bs[k][n] = *(const float4*)&g_WihT[(long long)(kk + k) * NP + n0 + n];
        }
        __syncthreads();
        #pragma unroll 4
        for (int k = 0; k < BK; k++) {
            float a[8];
            #pragma unroll
            for (int i = 0; i < 8; i++) a[i] = As[tm0 + i][k];
            unsigned long long bv[5];
            const unsigned long long* Bk = (const unsigned long long*)&Bs[k][tn0];
            #pragma unroll
            for (int u = 0; u < 5; u++) bv[u] = Bk[u];
            #pragma unroll
            for (int i = 0; i < 8; i++) {
                unsigned long long aa = bcast2(a[i]);
                #pragma unroll
                for (int u = 0; u < 5; u++) ffma2(acc[i][u], aa, bv[u]);
            }
        }
        __syncthreads();
    }
    #pragma unroll
    for (int i = 0; i < 8; i++) {
        long long row = (long long)(m0 + tm0 + i) * NP + n0 + tn0;
        #pragma unroll
        for (int u = 0; u < 5; u++) {
            float lo, hi; unpack2(acc[i][u], lo, hi);
            float2 v = make_float2(lo + bias[2 * u], hi + bias[2 * u + 1]);
            *(float2*)&g_XP[row + 2 * u] = v;
        }
    }
}

// -------- recurrent scan: 64 clusters x 2 CTAs, 8 batch per cluster --------
// CTA rank r holds W_hh rows j in [152r, 152r+152) transposed in smem (k-major).
// Per step: each CTA computes its h-half, writes it to BOTH CTAs' h buffers
// (local STS + st.shared::cluster to peer), then barrier.cluster.
__global__ __cluster_dims__(2, 1, 1) __launch_bounds__(STHREADS, 1)
void scan_kernel(float* __restrict__ out) {
    extern __shared__ float sm[];
    float* WT = sm;            // [300][152]
    float* H  = sm + WSZ;      // [2][304][8] double-buffered h, layout [k][b]
    int tid = threadIdx.x;
    unsigned rank;
    asm("mov.u32 %0, %%cluster_ctarank;" : "=r"(rank));
    int cid = blockIdx.x >> 1;

    const float* WTg = g_WT + rank * WSZ;
    for (int i = tid; i < WSZ; i += STHREADS) WT[i] = WTg[i];
    for (int i = tid; i < 2 * HBUF; i += STHREADS) H[i] = 0.f;
    asm volatile("barrier.cluster.arrive.aligned;" ::: "memory");
    asm volatile("barrier.cluster.wait.aligned;" ::: "memory");

    int jg = tid % 76, bg = tid / 76;   // 2 j's per thread, 4 b's per thread
    bool active = tid < 152;
    int j0 = jg * 2;
    int jglob = rank * JH + j0;         // global j of acc lane 0
    int bloc = bg * 4;                  // 0 or 4
    int bglob = cid * 8 + bloc;
    uint32_t hbase32 = smem_u32(H);
    unsigned peer = rank ^ 1u;
    int p = 0;

    for (int t = 0; t < SEQ; t++) {
        unsigned long long a0 = 0, a1 = 0, a2 = 0, a3 = 0;
        if (active) {
            const float* xr = g_XP + (long long)(t * BATCH + bglob) * NP + jglob;
            float2 x0 = *(const float2*)(xr);
            float2 x1 = *(const float2*)(xr + NP);
            float2 x2 = *(const float2*)(xr + 2 * NP);
            float2 x3 = *(const float2*)(xr + 3 * NP);
            a0 = pack2(x0.x, x0.y);
            a1 = pack2(x1.x, x1.y);
            a2 = pack2(x2.x, x2.y);
            a3 = pack2(x3.x, x3.y);
            const float* Hp = H + p * HBUF;
            #pragma unroll 5
            for (int k = 0; k < IDIM; k++) {
                unsigned long long w = *(const unsigned long long*)(WT + k * JH + j0);
                float4 h4 = *(const float4*)(Hp + k * HSTRIDE + bloc);
                ffma2(a0, w, bcast2(h4.x));
                ffma2(a1, w, bcast2(h4.y));
                ffma2(a2, w, bcast2(h4.z));
                ffma2(a3, w, bcast2(h4.w));
            }
            float v0l, v0h, v1l, v1h, v2l, v2h, v3l, v3h;
            unpack2(a0, v0l, v0h); unpack2(a1, v1l, v1h);
            unpack2(a2, v2l, v2h); unpack2(a3, v3l, v3h);
            float4 lo4 = make_float4(tanhf(v0l), tanhf(v1l), tanhf(v2l), tanhf(v3l));
            float4 hi4 = make_float4(tanhf(v0h), tanhf(v1h), tanhf(v2h), tanhf(v3h));
            int off0 = (1 - p) * HBUF + jglob * HSTRIDE + bloc;   // row j0
            int off1 = off0 + HSTRIDE;                            // row j0+1
            *(float4*)(H + off0) = lo4;
            *(float4*)(H + off1) = hi4;
            uint32_t r0 = hbase32 + off0 * 4;
            uint32_t r1 = hbase32 + off1 * 4;
            asm volatile("{ .reg .b32 ra; .reg .b64 d; mov.b64 d, {%2,%3}; "
                         "mapa.shared::cluster.u32 ra, %0, %1; st.shared::cluster.b64 [ra], d; }"
                         :: "r"(r0), "r"(peer), "f"(lo4.x), "f"(lo4.y) : "memory");
            asm volatile("{ .reg .b32 ra; .reg .b64 d; mov.b64 d, {%2,%3}; "
                         "mapa.shared::cluster.u32 ra, %0, %1; st.shared::cluster.b64 [ra], d; }"
                         :: "r"(r0 + 8u), "r"(peer), "f"(lo4.z), "f"(lo4.w) : "memory");
            asm volatile("{ .reg .b32 ra; .reg .b64 d; mov.b64 d, {%2,%3}; "
                         "mapa.shared::cluster.u32 ra, %0, %1; st.shared::cluster.b64 [ra], d; }"
                         :: "r"(r1), "r"(peer), "f"(hi4.x), "f"(hi4.y) : "memory");
            asm volatile("{ .reg .b32 ra; .reg .b64 d; mov.b64 d, {%2,%3}; "
                         "mapa.shared::cluster.u32 ra, %0, %1; st.shared::cluster.b64 [ra], d; }"
                         :: "r"(r1 + 8u), "r"(peer), "f"(hi4.z), "f"(hi4.w) : "memory");
        }
        asm volatile("barrier.cluster.arrive.aligned;" ::: "memory");
        asm volatile("barrier.cluster.wait.aligned;" ::: "memory");
        p ^= 1;
    }

    // write final h: each CTA writes its j-half for the cluster's 8 batches
    const float* Hf = H + p * HBUF;
    int cb0 = cid * 8;
    for (int idx = tid; idx < 8 * JH; idx += STHREADS) {
        int b = idx / JH, jj = idx % JH;
        int j = rank * JH + jj;
        if (j < HDIM) out[(long long)(cb0 + b) * HDIM + j] = Hf[j * HSTRIDE + b];
    }
}

extern "C" void kernel_launch(void* const* d_in, const int* in_sizes, int n_in,
                              void* d_out, int out_size) {
    const float* IN  = (const float*)d_in[0];
    const float* Wih = (const float*)d_in[1];
    const float* Whh = (const float*)d_in[2];
    const float* bih = (const float*)d_in[3];
    const float* bhh = (const float*)d_in[4];
    float* out = (float*)d_out;

    prep_kernel<<<(IDIM * NP + 255) / 256, 256>>>(Wih, Whh, bih, bhh);

    dim3 g(NP / BN, MTOT / BM);   // (2, 2048)
    gemm_xproj<<<g, 256>>>(IN);

    size_t smem = (size_t)(WSZ + 2 * HBUF) * sizeof(float);  // 201,856 B
    cudaFuncSetAttribute(scan_kernel, cudaFuncAttributeMaxDynamicSharedMemorySize, (int)smem);
    scan_kernel<<<128, STHREADS, smem>>>(out);
}